// round 2
// baseline (speedup 1.0000x reference)
#include <cuda_runtime.h>
#include <cuda_bf16.h>
#include <cstdint>

// ---------------------------------------------------------------------------
// Problem constants
// ---------------------------------------------------------------------------
#define BATCH   4
#define SEQ     2048
#define DMODEL  512
#define DSTATE  16
#define DCONV   4
#define DINNER  1024          // EXPAND * DMODEL
#define DTRANK  32
#define MROWS   (BATCH * SEQ) // 8192

// ---------------------------------------------------------------------------
// Scratch: single __device__ global, carved into stage buffers (floats)
// ---------------------------------------------------------------------------
#define OFF_XNORM  0u                                   // 8192*512
#define OFF_XZ     (OFF_XNORM + MROWS * DMODEL)         // 8192*2048
#define OFF_XCONV  (OFF_XZ    + MROWS * 2 * DINNER)     // 8192*1024
#define OFF_XDBL   (OFF_XCONV + MROWS * DINNER)         // 8192*64
#define OFF_DT     (OFF_XDBL  + MROWS * 64)             // 8192*1024
#define OFF_Y      (OFF_DT    + MROWS * DINNER)         // 8192*1024
#define SCRATCH_FLOATS (OFF_Y + MROWS * DINNER)

__device__ __align__(16) float g_scratch[SCRATCH_FLOATS];

// ---------------------------------------------------------------------------
// Helpers
// ---------------------------------------------------------------------------
__device__ __forceinline__ float silu_f(float v) {
    return v / (1.0f + __expf(-v));
}
__device__ __forceinline__ float softplus_f(float v) {
    return v > 20.0f ? v : log1pf(__expf(v));
}

// ---------------------------------------------------------------------------
// LayerNorm: one block per row of 512, 256 threads, float2 per thread
// ---------------------------------------------------------------------------
__global__ __launch_bounds__(256) void ln_kernel(
    const float* __restrict__ x,
    const float* __restrict__ gamma,
    const float* __restrict__ beta,
    float* __restrict__ out)
{
    const int row = blockIdx.x;
    const int tid = threadIdx.x;
    float2 v = reinterpret_cast<const float2*>(x + (size_t)row * DMODEL)[tid];

    float s  = v.x + v.y;
    float ss = v.x * v.x + v.y * v.y;

    #pragma unroll
    for (int off = 16; off; off >>= 1) {
        s  += __shfl_xor_sync(0xffffffffu, s,  off);
        ss += __shfl_xor_sync(0xffffffffu, ss, off);
    }
    __shared__ float shs[8], shss[8];
    const int w = tid >> 5, l = tid & 31;
    if (l == 0) { shs[w] = s; shss[w] = ss; }
    __syncthreads();
    if (w == 0) {
        s  = (l < 8) ? shs[l]  : 0.0f;
        ss = (l < 8) ? shss[l] : 0.0f;
        #pragma unroll
        for (int off = 4; off; off >>= 1) {
            s  += __shfl_xor_sync(0xffffffffu, s,  off);
            ss += __shfl_xor_sync(0xffffffffu, ss, off);
        }
        if (l == 0) { shs[0] = s; shss[0] = ss; }
    }
    __syncthreads();
    const float mean = shs[0] * (1.0f / DMODEL);
    const float var  = shss[0] * (1.0f / DMODEL) - mean * mean;
    const float inv  = rsqrtf(var + 1e-5f);

    float2 gg = reinterpret_cast<const float2*>(gamma)[tid];
    float2 bb = reinterpret_cast<const float2*>(beta)[tid];
    float2 o;
    o.x = (v.x - mean) * inv * gg.x + bb.x;
    o.y = (v.y - mean) * inv * gg.y + bb.y;
    reinterpret_cast<float2*>(out + (size_t)row * DMODEL)[tid] = o;
}

// ---------------------------------------------------------------------------
// SGEMM: C[M,N] = A[M,K] * B[N,K]^T   (row-major A with lda, weights B [N,K])
// 128x128 tile, BK=8, 256 threads, 8x8 per-thread register tile.
// EPI==1: out = softplus(acc + bias[col])   (dt projection)
// ---------------------------------------------------------------------------
template<int EPI>
__global__ __launch_bounds__(256) void sgemm128(
    const float* __restrict__ A, int lda,
    const float* __restrict__ B, int ldb,
    float* __restrict__ C, int ldc,
    int K,
    const float* __restrict__ bias)
{
    __shared__ __align__(16) float As[8][128];
    __shared__ __align__(16) float Bs[8][128];

    const int tid  = threadIdx.x;
    const int tx   = tid & 15;      // 0..15 -> 8 cols each
    const int ty   = tid >> 4;      // 0..15 -> 8 rows each
    const int brow = blockIdx.y * 128;
    const int bcol = blockIdx.x * 128;

    float acc[8][8];
    #pragma unroll
    for (int i = 0; i < 8; i++)
        #pragma unroll
        for (int j = 0; j < 8; j++) acc[i][j] = 0.0f;

    const int lr = tid >> 1;         // 0..127
    const int lk = (tid & 1) * 4;    // 0 or 4
    const float* Ap = A + (size_t)(brow + lr) * lda + lk;
    const float* Bp = B + (size_t)(bcol + lr) * ldb + lk;

    for (int k0 = 0; k0 < K; k0 += 8) {
        float4 av = *reinterpret_cast<const float4*>(Ap + k0);
        float4 bv = *reinterpret_cast<const float4*>(Bp + k0);
        As[lk + 0][lr] = av.x; As[lk + 1][lr] = av.y;
        As[lk + 2][lr] = av.z; As[lk + 3][lr] = av.w;
        Bs[lk + 0][lr] = bv.x; Bs[lk + 1][lr] = bv.y;
        Bs[lk + 2][lr] = bv.z; Bs[lk + 3][lr] = bv.w;
        __syncthreads();

        #pragma unroll
        for (int k = 0; k < 8; k++) {
            float4 a0 = *reinterpret_cast<const float4*>(&As[k][ty * 8]);
            float4 a1 = *reinterpret_cast<const float4*>(&As[k][ty * 8 + 4]);
            float4 b0 = *reinterpret_cast<const float4*>(&Bs[k][tx * 8]);
            float4 b1 = *reinterpret_cast<const float4*>(&Bs[k][tx * 8 + 4]);
            float a[8] = {a0.x, a0.y, a0.z, a0.w, a1.x, a1.y, a1.z, a1.w};
            float b[8] = {b0.x, b0.y, b0.z, b0.w, b1.x, b1.y, b1.z, b1.w};
            #pragma unroll
            for (int i = 0; i < 8; i++)
                #pragma unroll
                for (int j = 0; j < 8; j++) acc[i][j] += a[i] * b[j];
        }
        __syncthreads();
    }

    #pragma unroll
    for (int i = 0; i < 8; i++) {
        const size_t row = (size_t)(brow + ty * 8 + i);
        float* Cr = C + row * ldc + bcol + tx * 8;
        #pragma unroll
        for (int j = 0; j < 8; j += 4) {
            float4 o;
            if (EPI == 1) {
                const int col = bcol + tx * 8 + j;
                o.x = softplus_f(acc[i][j + 0] + bias[col + 0]);
                o.y = softplus_f(acc[i][j + 1] + bias[col + 1]);
                o.z = softplus_f(acc[i][j + 2] + bias[col + 2]);
                o.w = softplus_f(acc[i][j + 3] + bias[col + 3]);
            } else {
                o.x = acc[i][j + 0]; o.y = acc[i][j + 1];
                o.z = acc[i][j + 2]; o.w = acc[i][j + 3];
            }
            *reinterpret_cast<float4*>(Cr + j) = o;
        }
    }
}

// ---------------------------------------------------------------------------
// SGEMM 64x64 tile (for N=64 x_proj), BK=16, 256 threads, 4x4 per thread
// ---------------------------------------------------------------------------
__global__ __launch_bounds__(256) void sgemm64(
    const float* __restrict__ A, int lda,
    const float* __restrict__ B, int ldb,
    float* __restrict__ C, int ldc,
    int K)
{
    __shared__ __align__(16) float As[16][64];
    __shared__ __align__(16) float Bs[16][64];

    const int tid  = threadIdx.x;
    const int tx   = tid & 15;
    const int ty   = tid >> 4;
    const int brow = blockIdx.y * 64;
    const int bcol = blockIdx.x * 64;

    float acc[4][4];
    #pragma unroll
    for (int i = 0; i < 4; i++)
        #pragma unroll
        for (int j = 0; j < 4; j++) acc[i][j] = 0.0f;

    const int lr = tid >> 2;          // 0..63
    const int lk = (tid & 3) * 4;     // 0,4,8,12
    const float* Ap = A + (size_t)(brow + lr) * lda + lk;
    const float* Bp = B + (size_t)(bcol + lr) * ldb + lk;

    for (int k0 = 0; k0 < K; k0 += 16) {
        float4 av = *reinterpret_cast<const float4*>(Ap + k0);
        float4 bv = *reinterpret_cast<const float4*>(Bp + k0);
        As[lk + 0][lr] = av.x; As[lk + 1][lr] = av.y;
        As[lk + 2][lr] = av.z; As[lk + 3][lr] = av.w;
        Bs[lk + 0][lr] = bv.x; Bs[lk + 1][lr] = bv.y;
        Bs[lk + 2][lr] = bv.z; Bs[lk + 3][lr] = bv.w;
        __syncthreads();

        #pragma unroll
        for (int k = 0; k < 16; k++) {
            float4 a = *reinterpret_cast<const float4*>(&As[k][ty * 4]);
            float4 b = *reinterpret_cast<const float4*>(&Bs[k][tx * 4]);
            float av4[4] = {a.x, a.y, a.z, a.w};
            float bv4[4] = {b.x, b.y, b.z, b.w};
            #pragma unroll
            for (int i = 0; i < 4; i++)
                #pragma unroll
                for (int j = 0; j < 4; j++) acc[i][j] += av4[i] * bv4[j];
        }
        __syncthreads();
    }

    #pragma unroll
    for (int i = 0; i < 4; i++) {
        const size_t row = (size_t)(brow + ty * 4 + i);
        float4 o = {acc[i][0], acc[i][1], acc[i][2], acc[i][3]};
        *reinterpret_cast<float4*>(C + row * ldc + bcol + tx * 4) = o;
    }
}

// ---------------------------------------------------------------------------
// Depthwise causal conv (k=4) + bias + silu.
// x_in = columns [0,1024) of xz (row stride 2048).
// ---------------------------------------------------------------------------
__global__ __launch_bounds__(256) void conv_silu_kernel(
    const float* __restrict__ xz,
    const float* __restrict__ w,     // [DINNER,1,4]
    const float* __restrict__ cb,    // [DINNER]
    float* __restrict__ out)         // [MROWS, DINNER]
{
    const int i = blockIdx.x * blockDim.x + threadIdx.x;   // 8192*1024 threads
    const int d   = i & (DINNER - 1);
    const int row = i >> 10;
    const int t   = row & (SEQ - 1);

    const float* base = xz + (size_t)row * (2 * DINNER) + d;
    float acc = cb[d];
    #pragma unroll
    for (int k = 0; k < DCONV; k++) {
        const int tt = t - (DCONV - 1) + k;
        if (tt >= 0)
            acc += w[d * DCONV + k] * base[(long)(k - (DCONV - 1)) * (2 * DINNER)];
    }
    out[i] = silu_f(acc);
}

// ---------------------------------------------------------------------------
// Selective scan. One thread per (b, d, s): lane = state.
// 16-lane shuffle reduction for y = sum_s h*C. Fuses +x*D and *silu(z).
// Work items: BATCH * DINNER * DSTATE = 4*1024*16 = 65536 threads.
// ---------------------------------------------------------------------------
__global__ __launch_bounds__(256) void scan_kernel(
    const float* __restrict__ dtb,    // [MROWS, DINNER]
    const float* __restrict__ xc,     // [MROWS, DINNER]
    const float* __restrict__ xdbl,   // [MROWS, 64] (dt|B|C)
    const float* __restrict__ xz,     // [MROWS, 2048], z at cols [1024,2048)
    const float* __restrict__ A_log,  // [DINNER, DSTATE]
    const float* __restrict__ Dp,     // [DINNER]
    float* __restrict__ y)            // [MROWS, DINNER]
{
    const int gt    = blockIdx.x * blockDim.x + threadIdx.x;  // < 65536
    const int s     = gt & 15;
    const int group = gt >> 4;              // 0..4095 = b*1024 + d
    const int d     = group & (DINNER - 1);
    const int b     = group >> 10;          // 0..3

    const float A  = -expf(A_log[d * DSTATE + s]);
    const float Dv = Dp[d];

    float h = 0.0f;
    size_t base1024 = (size_t)b * SEQ * DINNER + d;
    size_t base64   = (size_t)b * SEQ * 64;
    size_t basez    = (size_t)b * SEQ * (2 * DINNER) + DINNER + d;

    for (int t = 0; t < SEQ; t++) {
        const float dt = dtb[base1024];
        const float xv = xc[base1024];
        const float Bv = xdbl[base64 + DTRANK + s];
        const float Cv = xdbl[base64 + DTRANK + DSTATE + s];

        h = h * __expf(dt * A) + dt * Bv * xv;

        float p = h * Cv;
        p += __shfl_xor_sync(0xffffffffu, p, 1, 16);
        p += __shfl_xor_sync(0xffffffffu, p, 2, 16);
        p += __shfl_xor_sync(0xffffffffu, p, 4, 16);
        p += __shfl_xor_sync(0xffffffffu, p, 8, 16);

        if (s == 0) {
            const float z = xz[basez];
            y[base1024] = (p + xv * Dv) * silu_f(z);
        }
        base1024 += DINNER;
        base64   += 64;
        basez    += 2 * DINNER;
    }
}

// ---------------------------------------------------------------------------
// Launch
// ---------------------------------------------------------------------------
extern "C" void kernel_launch(void* const* d_in, const int* in_sizes, int n_in,
                              void* d_out, int out_size)
{
    const float* x          = (const float*)d_in[0];
    const float* ln_gamma   = (const float*)d_in[1];
    const float* ln_beta    = (const float*)d_in[2];
    const float* in_proj_w  = (const float*)d_in[3];   // [2048, 512]
    const float* conv_w     = (const float*)d_in[4];   // [1024, 1, 4]
    const float* conv_b     = (const float*)d_in[5];   // [1024]
    const float* x_proj_w   = (const float*)d_in[6];   // [64, 1024]
    const float* dt_proj_w  = (const float*)d_in[7];   // [1024, 32]
    const float* dt_proj_b  = (const float*)d_in[8];   // [1024]
    const float* A_log      = (const float*)d_in[9];   // [1024, 16]
    const float* D_param    = (const float*)d_in[10];  // [1024]
    const float* out_proj_w = (const float*)d_in[11];  // [512, 1024]
    float* out = (float*)d_out;

    float* scratch = nullptr;
    cudaGetSymbolAddress((void**)&scratch, g_scratch);
    float* xnorm = scratch + OFF_XNORM;
    float* xz    = scratch + OFF_XZ;
    float* xconv = scratch + OFF_XCONV;
    float* xdbl  = scratch + OFF_XDBL;
    float* dtb   = scratch + OFF_DT;
    float* yb    = scratch + OFF_Y;

    // 1. layernorm
    ln_kernel<<<MROWS, 256>>>(x, ln_gamma, ln_beta, xnorm);

    // 2. xz = xnorm @ in_proj_w^T   (8192 x 2048, K=512)
    sgemm128<0><<<dim3(2 * DINNER / 128, MROWS / 128), 256>>>(
        xnorm, DMODEL, in_proj_w, DMODEL, xz, 2 * DINNER, DMODEL, nullptr);

    // 3. depthwise conv + silu -> xconv (8192 x 1024)
    conv_silu_kernel<<<(MROWS * DINNER) / 256, 256>>>(xz, conv_w, conv_b, xconv);

    // 4. x_dbl = xconv @ x_proj_w^T   (8192 x 64, K=1024)
    sgemm64<<<dim3(1, MROWS / 64), 256>>>(
        xconv, DINNER, x_proj_w, DINNER, xdbl, 64, DINNER);

    // 5. dt = softplus(x_dbl[:, :32] @ dt_proj_w^T + b)  (8192 x 1024, K=32)
    sgemm128<1><<<dim3(DINNER / 128, MROWS / 128), 256>>>(
        xdbl, 64, dt_proj_w, DTRANK, dtb, DINNER, DTRANK, dt_proj_b);

    // 6. selective scan (+ x*D, * silu(z)) -> yb
    //    BATCH*DINNER*DSTATE = 65536 threads (b,d,s)
    scan_kernel<<<(BATCH * DINNER * DSTATE) / 256, 256>>>(
        dtb, xconv, xdbl, xz, A_log, D_param, yb);

    // 7. out = yb @ out_proj_w^T   (8192 x 512, K=1024)
    sgemm128<0><<<dim3(DMODEL / 128, MROWS / 128), 256>>>(
        yb, DINNER, out_proj_w, DINNER, out, DMODEL, DINNER, nullptr);
}

// round 3
// speedup vs baseline: 1.1536x; 1.1536x over previous
#include <cuda_runtime.h>
#include <cuda_bf16.h>
#include <cstdint>

// ---------------------------------------------------------------------------
// Problem constants
// ---------------------------------------------------------------------------
#define BATCH   4
#define SEQ     2048
#define DMODEL  512
#define DSTATE  16
#define DCONV   4
#define DINNER  1024          // EXPAND * DMODEL
#define DTRANK  32
#define MROWS   (BATCH * SEQ) // 8192

// ---------------------------------------------------------------------------
// Scratch: single __device__ global, carved into stage buffers (floats)
// ---------------------------------------------------------------------------
#define OFF_XNORM  0u                                   // 8192*512
#define OFF_XZ     (OFF_XNORM + MROWS * DMODEL)         // 8192*2048
#define OFF_XCONV  (OFF_XZ    + MROWS * 2 * DINNER)     // 8192*1024
#define OFF_XDBL   (OFF_XCONV + MROWS * DINNER)         // 8192*64
#define OFF_DT     (OFF_XDBL  + MROWS * 64)             // 8192*1024
#define OFF_Y      (OFF_DT    + MROWS * DINNER)         // 8192*1024
#define SCRATCH_FLOATS (OFF_Y + MROWS * DINNER)

__device__ __align__(16) float g_scratch[SCRATCH_FLOATS];

// ---------------------------------------------------------------------------
// Helpers
// ---------------------------------------------------------------------------
__device__ __forceinline__ float silu_f(float v) {
    return v / (1.0f + __expf(-v));
}
__device__ __forceinline__ float softplus_f(float v) {
    return v > 20.0f ? v : log1pf(__expf(v));
}
__device__ __forceinline__ uint32_t f2tf32(float f) {
    uint32_t r;
    asm("cvt.rna.tf32.f32 %0, %1;" : "=r"(r) : "f"(f));
    return r;
}
__device__ __forceinline__ void mma_tf32(float c[4],
    uint32_t a0, uint32_t a1, uint32_t a2, uint32_t a3,
    uint32_t b0, uint32_t b1)
{
    asm volatile(
        "mma.sync.aligned.m16n8k8.row.col.f32.tf32.tf32.f32 "
        "{%0,%1,%2,%3}, {%4,%5,%6,%7}, {%8,%9}, {%0,%1,%2,%3};"
        : "+f"(c[0]), "+f"(c[1]), "+f"(c[2]), "+f"(c[3])
        : "r"(a0), "r"(a1), "r"(a2), "r"(a3), "r"(b0), "r"(b1));
}

// ---------------------------------------------------------------------------
// LayerNorm: one block per row of 512, 256 threads, float2 per thread
// ---------------------------------------------------------------------------
__global__ __launch_bounds__(256) void ln_kernel(
    const float* __restrict__ x,
    const float* __restrict__ gamma,
    const float* __restrict__ beta,
    float* __restrict__ out)
{
    const int row = blockIdx.x;
    const int tid = threadIdx.x;
    float2 v = reinterpret_cast<const float2*>(x + (size_t)row * DMODEL)[tid];

    float s  = v.x + v.y;
    float ss = v.x * v.x + v.y * v.y;

    #pragma unroll
    for (int off = 16; off; off >>= 1) {
        s  += __shfl_xor_sync(0xffffffffu, s,  off);
        ss += __shfl_xor_sync(0xffffffffu, ss, off);
    }
    __shared__ float shs[8], shss[8];
    const int w = tid >> 5, l = tid & 31;
    if (l == 0) { shs[w] = s; shss[w] = ss; }
    __syncthreads();
    if (w == 0) {
        s  = (l < 8) ? shs[l]  : 0.0f;
        ss = (l < 8) ? shss[l] : 0.0f;
        #pragma unroll
        for (int off = 4; off; off >>= 1) {
            s  += __shfl_xor_sync(0xffffffffu, s,  off);
            ss += __shfl_xor_sync(0xffffffffu, ss, off);
        }
        if (l == 0) { shs[0] = s; shss[0] = ss; }
    }
    __syncthreads();
    const float mean = shs[0] * (1.0f / DMODEL);
    const float var  = shss[0] * (1.0f / DMODEL) - mean * mean;
    const float inv  = rsqrtf(var + 1e-5f);

    float2 gg = reinterpret_cast<const float2*>(gamma)[tid];
    float2 bb = reinterpret_cast<const float2*>(beta)[tid];
    float2 o;
    o.x = (v.x - mean) * inv * gg.x + bb.x;
    o.y = (v.y - mean) * inv * gg.y + bb.y;
    reinterpret_cast<float2*>(out + (size_t)row * DMODEL)[tid] = o;
}

// ---------------------------------------------------------------------------
// TF32 tensor-core GEMM: C[M,N] = A[M,K] * B[N,K]^T
// 128x128 block tile, BK=16, double-buffered smem, 8 warps (2Mx4N),
// warp tile 64x32 via mma.sync.m16n8k8 tf32.
// Requires: M%128==0, N%128==0, K%16==0, lda/ldb %4==0.
// ---------------------------------------------------------------------------
__global__ __launch_bounds__(256, 2) void tf32_gemm(
    const float* __restrict__ A, int lda,
    const float* __restrict__ B, int ldb,
    float* __restrict__ C, int ldc,
    int K)
{
    __shared__ float As[2][128][20];
    __shared__ float Bs[2][128][20];

    const int tid  = threadIdx.x;
    const int warp = tid >> 5;
    const int lane = tid & 31;
    const int g    = lane >> 2;     // group id 0..7
    const int tig  = lane & 3;      // thread in group 0..3
    const int wM   = (warp & 1) * 64;
    const int wN   = (warp >> 1) * 32;
    const int brow = blockIdx.y * 128;
    const int bcol = blockIdx.x * 128;

    // global staging: each thread loads 8 floats of A and 8 of B per tile
    const int lr = tid >> 1;          // 0..127
    const int lc = (tid & 1) * 8;     // 0 or 8

    const float* Ag = A + (size_t)(brow + lr) * lda + lc;
    const float* Bg = B + (size_t)(bcol + lr) * ldb + lc;

    float acc[4][4][4];
    #pragma unroll
    for (int mt = 0; mt < 4; mt++)
        #pragma unroll
        for (int nt = 0; nt < 4; nt++)
            #pragma unroll
            for (int i = 0; i < 4; i++) acc[mt][nt][i] = 0.0f;

    const int KT = K >> 4;   // tiles of 16

    // prologue: load tile 0 into buffer 0
    {
        float4 a0 = *reinterpret_cast<const float4*>(Ag);
        float4 a1 = *reinterpret_cast<const float4*>(Ag + 4);
        float4 b0 = *reinterpret_cast<const float4*>(Bg);
        float4 b1 = *reinterpret_cast<const float4*>(Bg + 4);
        float4 ca0 = { __uint_as_float(f2tf32(a0.x)), __uint_as_float(f2tf32(a0.y)),
                       __uint_as_float(f2tf32(a0.z)), __uint_as_float(f2tf32(a0.w)) };
        float4 ca1 = { __uint_as_float(f2tf32(a1.x)), __uint_as_float(f2tf32(a1.y)),
                       __uint_as_float(f2tf32(a1.z)), __uint_as_float(f2tf32(a1.w)) };
        float4 cb0 = { __uint_as_float(f2tf32(b0.x)), __uint_as_float(f2tf32(b0.y)),
                       __uint_as_float(f2tf32(b0.z)), __uint_as_float(f2tf32(b0.w)) };
        float4 cb1 = { __uint_as_float(f2tf32(b1.x)), __uint_as_float(f2tf32(b1.y)),
                       __uint_as_float(f2tf32(b1.z)), __uint_as_float(f2tf32(b1.w)) };
        *reinterpret_cast<float4*>(&As[0][lr][lc])     = ca0;
        *reinterpret_cast<float4*>(&As[0][lr][lc + 4]) = ca1;
        *reinterpret_cast<float4*>(&Bs[0][lr][lc])     = cb0;
        *reinterpret_cast<float4*>(&Bs[0][lr][lc + 4]) = cb1;
    }
    __syncthreads();

    float4 sa0, sa1, sb0, sb1;

    for (int kt = 0; kt < KT; kt++) {
        const int p = kt & 1;

        if (kt + 1 < KT) {
            const float* Ap = Ag + (kt + 1) * 16;
            const float* Bp = Bg + (kt + 1) * 16;
            sa0 = *reinterpret_cast<const float4*>(Ap);
            sa1 = *reinterpret_cast<const float4*>(Ap + 4);
            sb0 = *reinterpret_cast<const float4*>(Bp);
            sb1 = *reinterpret_cast<const float4*>(Bp + 4);
        }

        #pragma unroll
        for (int ks = 0; ks < 2; ks++) {
            const int k0 = ks * 8;
            uint32_t af[4][4];
            uint32_t bf[4][2];
            #pragma unroll
            for (int mt = 0; mt < 4; mt++) {
                const int r = wM + mt * 16 + g;
                af[mt][0] = __float_as_uint(As[p][r    ][k0 + tig    ]);
                af[mt][1] = __float_as_uint(As[p][r + 8][k0 + tig    ]);
                af[mt][2] = __float_as_uint(As[p][r    ][k0 + tig + 4]);
                af[mt][3] = __float_as_uint(As[p][r + 8][k0 + tig + 4]);
            }
            #pragma unroll
            for (int nt = 0; nt < 4; nt++) {
                const int c = wN + nt * 8 + g;
                bf[nt][0] = __float_as_uint(Bs[p][c][k0 + tig    ]);
                bf[nt][1] = __float_as_uint(Bs[p][c][k0 + tig + 4]);
            }
            #pragma unroll
            for (int mt = 0; mt < 4; mt++)
                #pragma unroll
                for (int nt = 0; nt < 4; nt++)
                    mma_tf32(acc[mt][nt],
                             af[mt][0], af[mt][1], af[mt][2], af[mt][3],
                             bf[nt][0], bf[nt][1]);
        }

        if (kt + 1 < KT) {
            const int q = (kt + 1) & 1;
            float4 ca0 = { __uint_as_float(f2tf32(sa0.x)), __uint_as_float(f2tf32(sa0.y)),
                           __uint_as_float(f2tf32(sa0.z)), __uint_as_float(f2tf32(sa0.w)) };
            float4 ca1 = { __uint_as_float(f2tf32(sa1.x)), __uint_as_float(f2tf32(sa1.y)),
                           __uint_as_float(f2tf32(sa1.z)), __uint_as_float(f2tf32(sa1.w)) };
            float4 cb0 = { __uint_as_float(f2tf32(sb0.x)), __uint_as_float(f2tf32(sb0.y)),
                           __uint_as_float(f2tf32(sb0.z)), __uint_as_float(f2tf32(sb0.w)) };
            float4 cb1 = { __uint_as_float(f2tf32(sb1.x)), __uint_as_float(f2tf32(sb1.y)),
                           __uint_as_float(f2tf32(sb1.z)), __uint_as_float(f2tf32(sb1.w)) };
            *reinterpret_cast<float4*>(&As[q][lr][lc])     = ca0;
            *reinterpret_cast<float4*>(&As[q][lr][lc + 4]) = ca1;
            *reinterpret_cast<float4*>(&Bs[q][lr][lc])     = cb0;
            *reinterpret_cast<float4*>(&Bs[q][lr][lc + 4]) = cb1;
            __syncthreads();
        }
    }

    // epilogue
    #pragma unroll
    for (int mt = 0; mt < 4; mt++) {
        const int r0 = brow + wM + mt * 16 + g;
        #pragma unroll
        for (int nt = 0; nt < 4; nt++) {
            const int c0 = bcol + wN + nt * 8 + tig * 2;
            float2 lo = { acc[mt][nt][0], acc[mt][nt][1] };
            float2 hi = { acc[mt][nt][2], acc[mt][nt][3] };
            *reinterpret_cast<float2*>(&C[(size_t)r0 * ldc + c0])        = lo;
            *reinterpret_cast<float2*>(&C[(size_t)(r0 + 8) * ldc + c0])  = hi;
        }
    }
}

// ---------------------------------------------------------------------------
// SGEMM: C[M,N] = A[M,K] * B[N,K]^T (fp32 FFMA) — used for dt_proj (K=32)
// EPI==1: out = softplus(acc + bias[col])
// ---------------------------------------------------------------------------
template<int EPI>
__global__ __launch_bounds__(256) void sgemm128(
    const float* __restrict__ A, int lda,
    const float* __restrict__ B, int ldb,
    float* __restrict__ C, int ldc,
    int K,
    const float* __restrict__ bias)
{
    __shared__ __align__(16) float As[8][128];
    __shared__ __align__(16) float Bs[8][128];

    const int tid  = threadIdx.x;
    const int tx   = tid & 15;
    const int ty   = tid >> 4;
    const int brow = blockIdx.y * 128;
    const int bcol = blockIdx.x * 128;

    float acc[8][8];
    #pragma unroll
    for (int i = 0; i < 8; i++)
        #pragma unroll
        for (int j = 0; j < 8; j++) acc[i][j] = 0.0f;

    const int lr = tid >> 1;
    const int lk = (tid & 1) * 4;
    const float* Ap = A + (size_t)(brow + lr) * lda + lk;
    const float* Bp = B + (size_t)(bcol + lr) * ldb + lk;

    for (int k0 = 0; k0 < K; k0 += 8) {
        float4 av = *reinterpret_cast<const float4*>(Ap + k0);
        float4 bv = *reinterpret_cast<const float4*>(Bp + k0);
        As[lk + 0][lr] = av.x; As[lk + 1][lr] = av.y;
        As[lk + 2][lr] = av.z; As[lk + 3][lr] = av.w;
        Bs[lk + 0][lr] = bv.x; Bs[lk + 1][lr] = bv.y;
        Bs[lk + 2][lr] = bv.z; Bs[lk + 3][lr] = bv.w;
        __syncthreads();

        #pragma unroll
        for (int k = 0; k < 8; k++) {
            float4 a0 = *reinterpret_cast<const float4*>(&As[k][ty * 8]);
            float4 a1 = *reinterpret_cast<const float4*>(&As[k][ty * 8 + 4]);
            float4 b0 = *reinterpret_cast<const float4*>(&Bs[k][tx * 8]);
            float4 b1 = *reinterpret_cast<const float4*>(&Bs[k][tx * 8 + 4]);
            float a[8] = {a0.x, a0.y, a0.z, a0.w, a1.x, a1.y, a1.z, a1.w};
            float b[8] = {b0.x, b0.y, b0.z, b0.w, b1.x, b1.y, b1.z, b1.w};
            #pragma unroll
            for (int i = 0; i < 8; i++)
                #pragma unroll
                for (int j = 0; j < 8; j++) acc[i][j] += a[i] * b[j];
        }
        __syncthreads();
    }

    #pragma unroll
    for (int i = 0; i < 8; i++) {
        const size_t row = (size_t)(brow + ty * 8 + i);
        float* Cr = C + row * ldc + bcol + tx * 8;
        #pragma unroll
        for (int j = 0; j < 8; j += 4) {
            float4 o;
            if (EPI == 1) {
                const int col = bcol + tx * 8 + j;
                o.x = softplus_f(acc[i][j + 0] + bias[col + 0]);
                o.y = softplus_f(acc[i][j + 1] + bias[col + 1]);
                o.z = softplus_f(acc[i][j + 2] + bias[col + 2]);
                o.w = softplus_f(acc[i][j + 3] + bias[col + 3]);
            } else {
                o.x = acc[i][j + 0]; o.y = acc[i][j + 1];
                o.z = acc[i][j + 2]; o.w = acc[i][j + 3];
            }
            *reinterpret_cast<float4*>(Cr + j) = o;
        }
    }
}

// ---------------------------------------------------------------------------
// SGEMM 64x64 tile (for N=64 x_proj), BK=16, 256 threads, 4x4 per thread
// ---------------------------------------------------------------------------
__global__ __launch_bounds__(256) void sgemm64(
    const float* __restrict__ A, int lda,
    const float* __restrict__ B, int ldb,
    float* __restrict__ C, int ldc,
    int K)
{
    __shared__ __align__(16) float As[16][64];
    __shared__ __align__(16) float Bs[16][64];

    const int tid  = threadIdx.x;
    const int tx   = tid & 15;
    const int ty   = tid >> 4;
    const int brow = blockIdx.y * 64;
    const int bcol = blockIdx.x * 64;

    float acc[4][4];
    #pragma unroll
    for (int i = 0; i < 4; i++)
        #pragma unroll
        for (int j = 0; j < 4; j++) acc[i][j] = 0.0f;

    const int lr = tid >> 2;
    const int lk = (tid & 3) * 4;
    const float* Ap = A + (size_t)(brow + lr) * lda + lk;
    const float* Bp = B + (size_t)(bcol + lr) * ldb + lk;

    for (int k0 = 0; k0 < K; k0 += 16) {
        float4 av = *reinterpret_cast<const float4*>(Ap + k0);
        float4 bv = *reinterpret_cast<const float4*>(Bp + k0);
        As[lk + 0][lr] = av.x; As[lk + 1][lr] = av.y;
        As[lk + 2][lr] = av.z; As[lk + 3][lr] = av.w;
        Bs[lk + 0][lr] = bv.x; Bs[lk + 1][lr] = bv.y;
        Bs[lk + 2][lr] = bv.z; Bs[lk + 3][lr] = bv.w;
        __syncthreads();

        #pragma unroll
        for (int k = 0; k < 16; k++) {
            float4 a = *reinterpret_cast<const float4*>(&As[k][ty * 4]);
            float4 b = *reinterpret_cast<const float4*>(&Bs[k][tx * 4]);
            float av4[4] = {a.x, a.y, a.z, a.w};
            float bv4[4] = {b.x, b.y, b.z, b.w};
            #pragma unroll
            for (int i = 0; i < 4; i++)
                #pragma unroll
                for (int j = 0; j < 4; j++) acc[i][j] += av4[i] * bv4[j];
        }
        __syncthreads();
    }

    #pragma unroll
    for (int i = 0; i < 4; i++) {
        const size_t row = (size_t)(brow + ty * 4 + i);
        float4 o = {acc[i][0], acc[i][1], acc[i][2], acc[i][3]};
        *reinterpret_cast<float4*>(C + row * ldc + bcol + tx * 4) = o;
    }
}

// ---------------------------------------------------------------------------
// Depthwise causal conv (k=4) + bias + silu.
// ---------------------------------------------------------------------------
__global__ __launch_bounds__(256) void conv_silu_kernel(
    const float* __restrict__ xz,
    const float* __restrict__ w,
    const float* __restrict__ cb,
    float* __restrict__ out)
{
    const int i = blockIdx.x * blockDim.x + threadIdx.x;
    const int d   = i & (DINNER - 1);
    const int row = i >> 10;
    const int t   = row & (SEQ - 1);

    const float* base = xz + (size_t)row * (2 * DINNER) + d;
    float acc = cb[d];
    #pragma unroll
    for (int k = 0; k < DCONV; k++) {
        const int tt = t - (DCONV - 1) + k;
        if (tt >= 0)
            acc += w[d * DCONV + k] * base[(long)(k - (DCONV - 1)) * (2 * DINNER)];
    }
    out[i] = silu_f(acc);
}

// ---------------------------------------------------------------------------
// Selective scan. One thread per (b, d, s): lane = state.
// ---------------------------------------------------------------------------
__global__ __launch_bounds__(256) void scan_kernel(
    const float* __restrict__ dtb,
    const float* __restrict__ xc,
    const float* __restrict__ xdbl,
    const float* __restrict__ xz,
    const float* __restrict__ A_log,
    const float* __restrict__ Dp,
    float* __restrict__ y)
{
    const int gt    = blockIdx.x * blockDim.x + threadIdx.x;
    const int s     = gt & 15;
    const int group = gt >> 4;
    const int d     = group & (DINNER - 1);
    const int b     = group >> 10;

    const float A  = -expf(A_log[d * DSTATE + s]);
    const float Dv = Dp[d];

    float h = 0.0f;
    size_t base1024 = (size_t)b * SEQ * DINNER + d;
    size_t base64   = (size_t)b * SEQ * 64;
    size_t basez    = (size_t)b * SEQ * (2 * DINNER) + DINNER + d;

    for (int t = 0; t < SEQ; t++) {
        const float dt = dtb[base1024];
        const float xv = xc[base1024];
        const float Bv = xdbl[base64 + DTRANK + s];
        const float Cv = xdbl[base64 + DTRANK + DSTATE + s];

        h = h * __expf(dt * A) + dt * Bv * xv;

        float p = h * Cv;
        p += __shfl_xor_sync(0xffffffffu, p, 1, 16);
        p += __shfl_xor_sync(0xffffffffu, p, 2, 16);
        p += __shfl_xor_sync(0xffffffffu, p, 4, 16);
        p += __shfl_xor_sync(0xffffffffu, p, 8, 16);

        if (s == 0) {
            const float z = xz[basez];
            y[base1024] = (p + xv * Dv) * silu_f(z);
        }
        base1024 += DINNER;
        base64   += 64;
        basez    += 2 * DINNER;
    }
}

// ---------------------------------------------------------------------------
// Launch
// ---------------------------------------------------------------------------
extern "C" void kernel_launch(void* const* d_in, const int* in_sizes, int n_in,
                              void* d_out, int out_size)
{
    const float* x          = (const float*)d_in[0];
    const float* ln_gamma   = (const float*)d_in[1];
    const float* ln_beta    = (const float*)d_in[2];
    const float* in_proj_w  = (const float*)d_in[3];   // [2048, 512]
    const float* conv_w     = (const float*)d_in[4];   // [1024, 1, 4]
    const float* conv_b     = (const float*)d_in[5];   // [1024]
    const float* x_proj_w   = (const float*)d_in[6];   // [64, 1024]
    const float* dt_proj_w  = (const float*)d_in[7];   // [1024, 32]
    const float* dt_proj_b  = (const float*)d_in[8];   // [1024]
    const float* A_log      = (const float*)d_in[9];   // [1024, 16]
    const float* D_param    = (const float*)d_in[10];  // [1024]
    const float* out_proj_w = (const float*)d_in[11];  // [512, 1024]
    float* out = (float*)d_out;

    float* scratch = nullptr;
    cudaGetSymbolAddress((void**)&scratch, g_scratch);
    float* xnorm = scratch + OFF_XNORM;
    float* xz    = scratch + OFF_XZ;
    float* xconv = scratch + OFF_XCONV;
    float* xdbl  = scratch + OFF_XDBL;
    float* dtb   = scratch + OFF_DT;
    float* yb    = scratch + OFF_Y;

    // 1. layernorm
    ln_kernel<<<MROWS, 256>>>(x, ln_gamma, ln_beta, xnorm);

    // 2. xz = xnorm @ in_proj_w^T   (8192 x 2048, K=512) — tf32 tensor cores
    tf32_gemm<<<dim3(2 * DINNER / 128, MROWS / 128), 256>>>(
        xnorm, DMODEL, in_proj_w, DMODEL, xz, 2 * DINNER, DMODEL);

    // 3. depthwise conv + silu -> xconv (8192 x 1024)
    conv_silu_kernel<<<(MROWS * DINNER) / 256, 256>>>(xz, conv_w, conv_b, xconv);

    // 4. x_dbl = xconv @ x_proj_w^T   (8192 x 64, K=1024)
    sgemm64<<<dim3(1, MROWS / 64), 256>>>(
        xconv, DINNER, x_proj_w, DINNER, xdbl, 64, DINNER);

    // 5. dt = softplus(x_dbl[:, :32] @ dt_proj_w^T + b)  (8192 x 1024, K=32)
    sgemm128<1><<<dim3(DINNER / 128, MROWS / 128), 256>>>(
        xdbl, 64, dt_proj_w, DTRANK, dtb, DINNER, DTRANK, dt_proj_b);

    // 6. selective scan (+ x*D, * silu(z)) -> yb
    scan_kernel<<<(BATCH * DINNER * DSTATE) / 256, 256>>>(
        dtb, xconv, xdbl, xz, A_log, D_param, yb);

    // 7. out = yb @ out_proj_w^T   (8192 x 512, K=1024) — tf32 tensor cores
    tf32_gemm<<<dim3(DMODEL / 128, MROWS / 128), 256>>>(
        yb, DINNER, out_proj_w, DINNER, out, DMODEL, DINNER);
}

// round 4
// speedup vs baseline: 3.1289x; 2.7123x over previous
#include <cuda_runtime.h>
#include <cuda_bf16.h>
#include <cstdint>

// ---------------------------------------------------------------------------
// Problem constants
// ---------------------------------------------------------------------------
#define BATCH   4
#define SEQ     2048
#define DMODEL  512
#define DSTATE  16
#define DCONV   4
#define DINNER  1024          // EXPAND * DMODEL
#define DTRANK  32
#define MROWS   (BATCH * SEQ) // 8192
#define KSPLIT  4             // split-K for x_proj

// ---------------------------------------------------------------------------
// Scratch
// ---------------------------------------------------------------------------
#define OFF_XNORM  0u
#define OFF_XZ     (OFF_XNORM + MROWS * DMODEL)
#define OFF_XCONV  (OFF_XZ    + MROWS * 2 * DINNER)
#define OFF_XDBL   (OFF_XCONV + MROWS * DINNER)
#define OFF_DT     (OFF_XDBL  + MROWS * 64)
#define OFF_Y      (OFF_DT    + MROWS * DINNER)
#define OFF_P      (OFF_Y     + MROWS * DINNER)        // split-K partials
#define SCRATCH_FLOATS (OFF_P + KSPLIT * MROWS * 64)

__device__ __align__(16) float g_scratch[SCRATCH_FLOATS];

// ---------------------------------------------------------------------------
// Helpers
// ---------------------------------------------------------------------------
__device__ __forceinline__ float silu_f(float v) {
    return v / (1.0f + __expf(-v));
}
__device__ __forceinline__ float softplus_f(float v) {
    return v > 20.0f ? v : __logf(1.0f + __expf(v));
}
__device__ __forceinline__ uint32_t f2tf32(float f) {
    uint32_t r;
    asm("cvt.rna.tf32.f32 %0, %1;" : "=r"(r) : "f"(f));
    return r;
}
__device__ __forceinline__ void mma_tf32(float c[4],
    uint32_t a0, uint32_t a1, uint32_t a2, uint32_t a3,
    uint32_t b0, uint32_t b1)
{
    asm volatile(
        "mma.sync.aligned.m16n8k8.row.col.f32.tf32.tf32.f32 "
        "{%0,%1,%2,%3}, {%4,%5,%6,%7}, {%8,%9}, {%0,%1,%2,%3};"
        : "+f"(c[0]), "+f"(c[1]), "+f"(c[2]), "+f"(c[3])
        : "r"(a0), "r"(a1), "r"(a2), "r"(a3), "r"(b0), "r"(b1));
}
__device__ __forceinline__ void cp16(void* smem, const void* gmem) {
    uint32_t s = (uint32_t)__cvta_generic_to_shared(smem);
    asm volatile("cp.async.cg.shared.global [%0], [%1], 16;" :: "r"(s), "l"(gmem));
}
#define CP_COMMIT() asm volatile("cp.async.commit_group;")
#define CP_WAIT(n)  asm volatile("cp.async.wait_group %0;" :: "n"(n))

// ---------------------------------------------------------------------------
// LayerNorm
// ---------------------------------------------------------------------------
__global__ __launch_bounds__(256) void ln_kernel(
    const float* __restrict__ x,
    const float* __restrict__ gamma,
    const float* __restrict__ beta,
    float* __restrict__ out)
{
    const int row = blockIdx.x;
    const int tid = threadIdx.x;
    float2 v = reinterpret_cast<const float2*>(x + (size_t)row * DMODEL)[tid];

    float s  = v.x + v.y;
    float ss = v.x * v.x + v.y * v.y;

    #pragma unroll
    for (int off = 16; off; off >>= 1) {
        s  += __shfl_xor_sync(0xffffffffu, s,  off);
        ss += __shfl_xor_sync(0xffffffffu, ss, off);
    }
    __shared__ float shs[8], shss[8];
    const int w = tid >> 5, l = tid & 31;
    if (l == 0) { shs[w] = s; shss[w] = ss; }
    __syncthreads();
    if (w == 0) {
        s  = (l < 8) ? shs[l]  : 0.0f;
        ss = (l < 8) ? shss[l] : 0.0f;
        #pragma unroll
        for (int off = 4; off; off >>= 1) {
            s  += __shfl_xor_sync(0xffffffffu, s,  off);
            ss += __shfl_xor_sync(0xffffffffu, ss, off);
        }
        if (l == 0) { shs[0] = s; shss[0] = ss; }
    }
    __syncthreads();
    const float mean = shs[0] * (1.0f / DMODEL);
    const float var  = shss[0] * (1.0f / DMODEL) - mean * mean;
    const float inv  = rsqrtf(var + 1e-5f);

    float2 gg = reinterpret_cast<const float2*>(gamma)[tid];
    float2 bb = reinterpret_cast<const float2*>(beta)[tid];
    float2 o;
    o.x = (v.x - mean) * inv * gg.x + bb.x;
    o.y = (v.y - mean) * inv * gg.y + bb.y;
    reinterpret_cast<float2*>(out + (size_t)row * DMODEL)[tid] = o;
}

// ---------------------------------------------------------------------------
// TF32 tensor-core GEMM, 4-stage cp.async pipeline.
// C[M,N] = A[M,K] * B[N,K]^T. 128x128 tile, BK=16, 8 warps (2Mx4N),
// warp 64x32 via mma.sync.m16n8k8 tf32. Dynamic smem: 4*2*128*20*4 = 81920 B.
// ---------------------------------------------------------------------------
#define GSTAGES 4
#define STG_F   (128 * 20)     // floats per stage per operand

__global__ __launch_bounds__(256, 2) void tf32_gemm(
    const float* __restrict__ A, int lda,
    const float* __restrict__ B, int ldb,
    float* __restrict__ C, int ldc,
    int K)
{
    extern __shared__ float sm[];
    float (*As)[128][20] = reinterpret_cast<float(*)[128][20]>(sm);
    float (*Bs)[128][20] = reinterpret_cast<float(*)[128][20]>(sm + GSTAGES * STG_F);

    const int tid  = threadIdx.x;
    const int warp = tid >> 5;
    const int lane = tid & 31;
    const int g    = lane >> 2;
    const int tig  = lane & 3;
    const int wM   = (warp & 1) * 64;
    const int wN   = (warp >> 1) * 32;
    const int brow = blockIdx.y * 128;
    const int bcol = blockIdx.x * 128;

    const int lr = tid >> 1;
    const int lc = (tid & 1) * 8;
    const float* Ag = A + (size_t)(brow + lr) * lda + lc;
    const float* Bg = B + (size_t)(bcol + lr) * ldb + lc;

    float acc[4][4][4];
    #pragma unroll
    for (int mt = 0; mt < 4; mt++)
        #pragma unroll
        for (int nt = 0; nt < 4; nt++)
            #pragma unroll
            for (int i = 0; i < 4; i++) acc[mt][nt][i] = 0.0f;

    const int KT = K >> 4;

#define LOAD_STAGE(kt, st) do {                                   \
        const float* _Ap = Ag + (kt) * 16;                        \
        const float* _Bp = Bg + (kt) * 16;                        \
        cp16(&As[st][lr][lc],     _Ap);                           \
        cp16(&As[st][lr][lc + 4], _Ap + 4);                       \
        cp16(&Bs[st][lr][lc],     _Bp);                           \
        cp16(&Bs[st][lr][lc + 4], _Bp + 4);                       \
    } while (0)

    // prologue: stages 0..GSTAGES-2
    #pragma unroll
    for (int s0 = 0; s0 < GSTAGES - 1; s0++) {
        if (s0 < KT) LOAD_STAGE(s0, s0);
        CP_COMMIT();
    }

    for (int kt = 0; kt < KT; kt++) {
        CP_WAIT(GSTAGES - 2);
        __syncthreads();

        if (kt + GSTAGES - 1 < KT)
            LOAD_STAGE(kt + GSTAGES - 1, (kt + GSTAGES - 1) % GSTAGES);
        CP_COMMIT();

        const int p = kt % GSTAGES;
        #pragma unroll
        for (int ks = 0; ks < 2; ks++) {
            const int k0 = ks * 8;
            uint32_t af[4][4];
            uint32_t bf[4][2];
            #pragma unroll
            for (int mt = 0; mt < 4; mt++) {
                const int r = wM + mt * 16 + g;
                af[mt][0] = f2tf32(As[p][r    ][k0 + tig    ]);
                af[mt][1] = f2tf32(As[p][r + 8][k0 + tig    ]);
                af[mt][2] = f2tf32(As[p][r    ][k0 + tig + 4]);
                af[mt][3] = f2tf32(As[p][r + 8][k0 + tig + 4]);
            }
            #pragma unroll
            for (int nt = 0; nt < 4; nt++) {
                const int c = wN + nt * 8 + g;
                bf[nt][0] = f2tf32(Bs[p][c][k0 + tig    ]);
                bf[nt][1] = f2tf32(Bs[p][c][k0 + tig + 4]);
            }
            #pragma unroll
            for (int mt = 0; mt < 4; mt++)
                #pragma unroll
                for (int nt = 0; nt < 4; nt++)
                    mma_tf32(acc[mt][nt],
                             af[mt][0], af[mt][1], af[mt][2], af[mt][3],
                             bf[nt][0], bf[nt][1]);
        }
        __syncthreads();
    }

    #pragma unroll
    for (int mt = 0; mt < 4; mt++) {
        const int r0 = brow + wM + mt * 16 + g;
        #pragma unroll
        for (int nt = 0; nt < 4; nt++) {
            const int c0 = bcol + wN + nt * 8 + tig * 2;
            float2 lo = { acc[mt][nt][0], acc[mt][nt][1] };
            float2 hi = { acc[mt][nt][2], acc[mt][nt][3] };
            *reinterpret_cast<float2*>(&C[(size_t)r0 * ldc + c0])       = lo;
            *reinterpret_cast<float2*>(&C[(size_t)(r0 + 8) * ldc + c0]) = hi;
        }
    }
#undef LOAD_STAGE
}
#define GEMM_SMEM (GSTAGES * STG_F * 2 * (int)sizeof(float))

// ---------------------------------------------------------------------------
// SGEMM 128x128 FFMA (dt_proj, K=32) with softplus+bias epilogue
// ---------------------------------------------------------------------------
template<int EPI>
__global__ __launch_bounds__(256) void sgemm128(
    const float* __restrict__ A, int lda,
    const float* __restrict__ B, int ldb,
    float* __restrict__ C, int ldc,
    int K,
    const float* __restrict__ bias)
{
    __shared__ __align__(16) float As[8][128];
    __shared__ __align__(16) float Bs[8][128];

    const int tid  = threadIdx.x;
    const int tx   = tid & 15;
    const int ty   = tid >> 4;
    const int brow = blockIdx.y * 128;
    const int bcol = blockIdx.x * 128;

    float acc[8][8];
    #pragma unroll
    for (int i = 0; i < 8; i++)
        #pragma unroll
        for (int j = 0; j < 8; j++) acc[i][j] = 0.0f;

    const int lr = tid >> 1;
    const int lk = (tid & 1) * 4;
    const float* Ap = A + (size_t)(brow + lr) * lda + lk;
    const float* Bp = B + (size_t)(bcol + lr) * ldb + lk;

    for (int k0 = 0; k0 < K; k0 += 8) {
        float4 av = *reinterpret_cast<const float4*>(Ap + k0);
        float4 bv = *reinterpret_cast<const float4*>(Bp + k0);
        As[lk + 0][lr] = av.x; As[lk + 1][lr] = av.y;
        As[lk + 2][lr] = av.z; As[lk + 3][lr] = av.w;
        Bs[lk + 0][lr] = bv.x; Bs[lk + 1][lr] = bv.y;
        Bs[lk + 2][lr] = bv.z; Bs[lk + 3][lr] = bv.w;
        __syncthreads();

        #pragma unroll
        for (int k = 0; k < 8; k++) {
            float4 a0 = *reinterpret_cast<const float4*>(&As[k][ty * 8]);
            float4 a1 = *reinterpret_cast<const float4*>(&As[k][ty * 8 + 4]);
            float4 b0 = *reinterpret_cast<const float4*>(&Bs[k][tx * 8]);
            float4 b1 = *reinterpret_cast<const float4*>(&Bs[k][tx * 8 + 4]);
            float a[8] = {a0.x, a0.y, a0.z, a0.w, a1.x, a1.y, a1.z, a1.w};
            float b[8] = {b0.x, b0.y, b0.z, b0.w, b1.x, b1.y, b1.z, b1.w};
            #pragma unroll
            for (int i = 0; i < 8; i++)
                #pragma unroll
                for (int j = 0; j < 8; j++) acc[i][j] += a[i] * b[j];
        }
        __syncthreads();
    }

    #pragma unroll
    for (int i = 0; i < 8; i++) {
        const size_t row = (size_t)(brow + ty * 8 + i);
        float* Cr = C + row * ldc + bcol + tx * 8;
        #pragma unroll
        for (int j = 0; j < 8; j += 4) {
            float4 o;
            if (EPI == 1) {
                const int col = bcol + tx * 8 + j;
                o.x = softplus_f(acc[i][j + 0] + bias[col + 0]);
                o.y = softplus_f(acc[i][j + 1] + bias[col + 1]);
                o.z = softplus_f(acc[i][j + 2] + bias[col + 2]);
                o.w = softplus_f(acc[i][j + 3] + bias[col + 3]);
            } else {
                o.x = acc[i][j + 0]; o.y = acc[i][j + 1];
                o.z = acc[i][j + 2]; o.w = acc[i][j + 3];
            }
            *reinterpret_cast<float4*>(Cr + j) = o;
        }
    }
}

// ---------------------------------------------------------------------------
// x_proj GEMM, split-K: grid (KSPLIT, MROWS/64). Each block: 64x64 tile over
// K/KSPLIT, writes its partial slice. Deterministic (no atomics).
// ---------------------------------------------------------------------------
__global__ __launch_bounds__(256) void sgemm64_splitk(
    const float* __restrict__ A, int lda,
    const float* __restrict__ B, int ldb,
    float* __restrict__ P)      // [KSPLIT][MROWS][64]
{
    __shared__ __align__(16) float As[16][64];
    __shared__ __align__(16) float Bs[16][64];

    const int KC = DINNER / KSPLIT;            // 256
    const int kslice = blockIdx.x;
    const float* Ak = A + kslice * KC;
    const float* Bk = B + kslice * KC;
    float* C = P + (size_t)kslice * MROWS * 64;

    const int tid  = threadIdx.x;
    const int tx   = tid & 15;
    const int ty   = tid >> 4;
    const int brow = blockIdx.y * 64;

    float acc[4][4];
    #pragma unroll
    for (int i = 0; i < 4; i++)
        #pragma unroll
        for (int j = 0; j < 4; j++) acc[i][j] = 0.0f;

    const int lr = tid >> 2;
    const int lk = (tid & 3) * 4;
    const float* Ap = Ak + (size_t)(brow + lr) * lda + lk;
    const float* Bp = Bk + (size_t)lr * ldb + lk;

    for (int k0 = 0; k0 < KC; k0 += 16) {
        float4 av = *reinterpret_cast<const float4*>(Ap + k0);
        float4 bv = *reinterpret_cast<const float4*>(Bp + k0);
        As[lk + 0][lr] = av.x; As[lk + 1][lr] = av.y;
        As[lk + 2][lr] = av.z; As[lk + 3][lr] = av.w;
        Bs[lk + 0][lr] = bv.x; Bs[lk + 1][lr] = bv.y;
        Bs[lk + 2][lr] = bv.z; Bs[lk + 3][lr] = bv.w;
        __syncthreads();

        #pragma unroll
        for (int k = 0; k < 16; k++) {
            float4 a = *reinterpret_cast<const float4*>(&As[k][ty * 4]);
            float4 b = *reinterpret_cast<const float4*>(&Bs[k][tx * 4]);
            float av4[4] = {a.x, a.y, a.z, a.w};
            float bv4[4] = {b.x, b.y, b.z, b.w};
            #pragma unroll
            for (int i = 0; i < 4; i++)
                #pragma unroll
                for (int j = 0; j < 4; j++) acc[i][j] += av4[i] * bv4[j];
        }
        __syncthreads();
    }

    #pragma unroll
    for (int i = 0; i < 4; i++) {
        const size_t row = (size_t)(brow + ty * 4 + i);
        float4 o = {acc[i][0], acc[i][1], acc[i][2], acc[i][3]};
        *reinterpret_cast<float4*>(C + row * 64 + tx * 4) = o;
    }
}

__global__ __launch_bounds__(256) void splitk_reduce(
    const float* __restrict__ P, float* __restrict__ out)
{
    const int i = blockIdx.x * blockDim.x + threadIdx.x;   // MROWS*64
    float s = 0.0f;
    #pragma unroll
    for (int k = 0; k < KSPLIT; k++)
        s += P[(size_t)k * MROWS * 64 + i];
    out[i] = s;
}

// ---------------------------------------------------------------------------
// Depthwise causal conv (k=4) + bias + silu
// ---------------------------------------------------------------------------
__global__ __launch_bounds__(256) void conv_silu_kernel(
    const float* __restrict__ xz,
    const float* __restrict__ w,
    const float* __restrict__ cb,
    float* __restrict__ out)
{
    const int i = blockIdx.x * blockDim.x + threadIdx.x;
    const int d   = i & (DINNER - 1);
    const int row = i >> 10;
    const int t   = row & (SEQ - 1);

    const float* base = xz + (size_t)row * (2 * DINNER) + d;
    float acc = cb[d];
    #pragma unroll
    for (int k = 0; k < DCONV; k++) {
        const int tt = t - (DCONV - 1) + k;
        if (tt >= 0)
            acc += w[d * DCONV + k] * base[(long)(k - (DCONV - 1)) * (2 * DINNER)];
    }
    out[i] = silu_f(acc);
}

// ---------------------------------------------------------------------------
// Selective scan, software-pipelined: batch-load 8 timesteps, then consume.
// One thread per (b, d, s): lane = state (16-lane groups).
// ---------------------------------------------------------------------------
#define SUNROLL 8
__global__ __launch_bounds__(128) void scan_kernel(
    const float* __restrict__ dtb,
    const float* __restrict__ xc,
    const float* __restrict__ xdbl,
    const float* __restrict__ xz,
    const float* __restrict__ A_log,
    const float* __restrict__ Dp,
    float* __restrict__ y)
{
    const int gt    = blockIdx.x * blockDim.x + threadIdx.x;  // < 65536
    const int s     = gt & 15;
    const int group = gt >> 4;
    const int d     = group & (DINNER - 1);
    const int b     = group >> 10;

    const float A  = -expf(A_log[d * DSTATE + s]);
    const float Dv = Dp[d];

    float h = 0.0f;
    size_t base1024 = (size_t)b * SEQ * DINNER + d;
    size_t base64   = (size_t)b * SEQ * 64;
    size_t basez    = (size_t)b * SEQ * (2 * DINNER) + DINNER + d;

    for (int t0 = 0; t0 < SEQ; t0 += SUNROLL) {
        float dtv[SUNROLL], xvv[SUNROLL], bvv[SUNROLL], cvv[SUNROLL], zvv[SUNROLL];
        #pragma unroll
        for (int u = 0; u < SUNROLL; u++) {
            dtv[u] = dtb[base1024 + (size_t)u * DINNER];
            xvv[u] = xc [base1024 + (size_t)u * DINNER];
            bvv[u] = xdbl[base64 + u * 64 + DTRANK + s];
            cvv[u] = xdbl[base64 + u * 64 + DTRANK + DSTATE + s];
            zvv[u] = xz [basez + (size_t)u * (2 * DINNER)];
        }
        #pragma unroll
        for (int u = 0; u < SUNROLL; u++) {
            h = h * __expf(dtv[u] * A) + dtv[u] * bvv[u] * xvv[u];
            float p = h * cvv[u];
            p += __shfl_xor_sync(0xffffffffu, p, 1, 16);
            p += __shfl_xor_sync(0xffffffffu, p, 2, 16);
            p += __shfl_xor_sync(0xffffffffu, p, 4, 16);
            p += __shfl_xor_sync(0xffffffffu, p, 8, 16);
            if (s == 0)
                y[base1024 + (size_t)u * DINNER] = (p + xvv[u] * Dv) * silu_f(zvv[u]);
        }
        base1024 += (size_t)SUNROLL * DINNER;
        base64   += SUNROLL * 64;
        basez    += (size_t)SUNROLL * (2 * DINNER);
    }
}

// ---------------------------------------------------------------------------
// Launch
// ---------------------------------------------------------------------------
extern "C" void kernel_launch(void* const* d_in, const int* in_sizes, int n_in,
                              void* d_out, int out_size)
{
    const float* x          = (const float*)d_in[0];
    const float* ln_gamma   = (const float*)d_in[1];
    const float* ln_beta    = (const float*)d_in[2];
    const float* in_proj_w  = (const float*)d_in[3];
    const float* conv_w     = (const float*)d_in[4];
    const float* conv_b     = (const float*)d_in[5];
    const float* x_proj_w   = (const float*)d_in[6];
    const float* dt_proj_w  = (const float*)d_in[7];
    const float* dt_proj_b  = (const float*)d_in[8];
    const float* A_log      = (const float*)d_in[9];
    const float* D_param    = (const float*)d_in[10];
    const float* out_proj_w = (const float*)d_in[11];
    float* out = (float*)d_out;

    float* scratch = nullptr;
    cudaGetSymbolAddress((void**)&scratch, g_scratch);
    float* xnorm = scratch + OFF_XNORM;
    float* xz    = scratch + OFF_XZ;
    float* xconv = scratch + OFF_XCONV;
    float* xdbl  = scratch + OFF_XDBL;
    float* dtb   = scratch + OFF_DT;
    float* yb    = scratch + OFF_Y;
    float* part  = scratch + OFF_P;

    static bool attr_set = false;
    if (!attr_set) {
        cudaFuncSetAttribute(tf32_gemm,
            cudaFuncAttributeMaxDynamicSharedMemorySize, GEMM_SMEM);
        attr_set = true;
    }

    // 1. layernorm
    ln_kernel<<<MROWS, 256>>>(x, ln_gamma, ln_beta, xnorm);

    // 2. xz = xnorm @ in_proj_w^T  (8192 x 2048, K=512)
    tf32_gemm<<<dim3(2 * DINNER / 128, MROWS / 128), 256, GEMM_SMEM>>>(
        xnorm, DMODEL, in_proj_w, DMODEL, xz, 2 * DINNER, DMODEL);

    // 3. depthwise conv + silu
    conv_silu_kernel<<<(MROWS * DINNER) / 256, 256>>>(xz, conv_w, conv_b, xconv);

    // 4. x_dbl = xconv @ x_proj_w^T  (8192 x 64, K=1024), split-K
    sgemm64_splitk<<<dim3(KSPLIT, MROWS / 64), 256>>>(
        xconv, DINNER, x_proj_w, DINNER, part);
    splitk_reduce<<<(MROWS * 64) / 256, 256>>>(part, xdbl);

    // 5. dt = softplus(x_dbl[:, :32] @ dt_proj_w^T + b)
    sgemm128<1><<<dim3(DINNER / 128, MROWS / 128), 256>>>(
        xdbl, 64, dt_proj_w, DTRANK, dtb, DINNER, DTRANK, dt_proj_b);

    // 6. selective scan
    scan_kernel<<<(BATCH * DINNER * DSTATE) / 128, 128>>>(
        dtb, xconv, xdbl, xz, A_log, D_param, yb);

    // 7. out = yb @ out_proj_w^T  (8192 x 512, K=1024)
    tf32_gemm<<<dim3(DMODEL / 128, MROWS / 128), 256, GEMM_SMEM>>>(
        yb, DINNER, out_proj_w, DINNER, out, DMODEL, DINNER);
}